// round 2
// baseline (speedup 1.0000x reference)
#include <cuda_runtime.h>
#include <math.h>

#define BATCH 8
#define N 2048
#define BN (BATCH * N)
#define TOTE (BATCH * N * N)          // 33554432 elements
#define NPART 16
#define NITER 50

#define EPSF   0.01f
#define BIGF   1e20f
#define HUGEF  1e30f
#define SMALLF 1e-7f
#define DXY    (1.0f / 2048.0f)

static constexpr float INVE = 1.0f / 0.01f;                          // 1/eps
static constexpr float CS   = (1.0f / 0.01f) * (1.0f / 16777216.0f); // inv_eps * 2^-24
static constexpr float PC   = 1.0f / (1.0f + 0.01f);                 // p_coef

// ---------------- device state (single big buffer, phase-aliased) ----------------
// Phase 1 (iteration loop): [0, 64MB) = u16 high bits of 24-bit fixed C
//                           [64MB, 96MB) = u8 low bits
// Phase 2 (final pass):     whole buffer = fallback fp32 K target (compressed C dead)
static __device__ float4 g_buf[TOTE / 4];        // 128 MB
static __device__ float g_u[2][BN];
static __device__ float g_v[2][BN];
static __device__ float g_a[BN];
static __device__ float g_bnew[BN];
static __device__ float g_part[NPART][BN];
static __device__ float g_rowsum[BN];
static __device__ float g_rowkc[BN];
static __device__ unsigned g_maxa[64];
static __device__ unsigned g_maxb[64];

__device__ __forceinline__ unsigned short* chi_ptr() {
    return (unsigned short*)g_buf;
}
__device__ __forceinline__ unsigned char* clo_ptr() {
    return (unsigned char*)g_buf + (size_t)TOTE * 2;
}

__device__ __forceinline__ float warp_sum(float x) {
#pragma unroll
    for (int o = 16; o; o >>= 1) x += __shfl_xor_sync(0xFFFFFFFFu, x, o);
    return x;
}

// ---------------- init ----------------
__global__ void init_kernel() {
    int g = blockIdx.x * 256 + threadIdx.x;
    if (g < BN) {
        g_u[0][g] = 0.0f;
        g_v[0][g] = 0.0f;
        g_bnew[g] = 1.0f;
    }
    if (g < 64) { g_maxa[g] = 0u; g_maxb[g] = 0u; }
}

// ---------------- compress C to 24-bit fixed point ----------------
__global__ void __launch_bounds__(256) compress_kernel(const float* __restrict__ C) {
    size_t idx = (size_t)blockIdx.x * 256 + threadIdx.x;   // covers TOTE/4
    float4 c = ((const float4*)C)[idx];
    unsigned q0 = (unsigned)(c.x * 16777216.0f);
    unsigned q1 = (unsigned)(c.y * 16777216.0f);
    unsigned q2 = (unsigned)(c.z * 16777216.0f);
    unsigned q3 = (unsigned)(c.w * 16777216.0f);
    q0 = q0 > 0xFFFFFFu ? 0xFFFFFFu : q0;
    q1 = q1 > 0xFFFFFFu ? 0xFFFFFFu : q1;
    q2 = q2 > 0xFFFFFFu ? 0xFFFFFFu : q2;
    q3 = q3 > 0xFFFFFFu ? 0xFFFFFFu : q3;
    ushort4 h = make_ushort4((unsigned short)(q0 >> 8), (unsigned short)(q1 >> 8),
                             (unsigned short)(q2 >> 8), (unsigned short)(q3 >> 8));
    ((ushort4*)chi_ptr())[idx] = h;
    unsigned l = (q0 & 0xFFu) | ((q1 & 0xFFu) << 8) | ((q2 & 0xFFu) << 16) | ((q3 & 0xFFu) << 24);
    ((unsigned*)clo_ptr())[idx] = l;
}

// ---------------- row pass: apply prev absorb, compute s -> a ----------------
__global__ void __launch_bounds__(256) row_kernel(int it) {
    __shared__ float sv[N];
    __shared__ float sb[N];
    __shared__ float swm[8];
    const int b   = blockIdx.x >> 8;
    const int rb  = blockIdx.x & 255;
    const int tid = threadIdx.x;
    const float* __restrict__ uIn  = g_u[it & 1];
    float* __restrict__ uOut       = g_u[(it + 1) & 1];
    const float* __restrict__ vIn  = g_v[it & 1];
    float* __restrict__ vOut       = g_v[(it + 1) & 1];
    const int prev = (it == 0) ? 63 : (it - 1);
    const bool pabs = (__uint_as_float(g_maxa[prev]) > BIGF) ||
                      (__uint_as_float(g_maxb[prev]) > BIGF);
    const int base = b * N;

    for (int j = tid; j < N; j += 256) {
        float v  = vIn[base + j];
        float bn = g_bnew[base + j];
        float vn, bd;
        if (pabs) { vn = v + EPSF * logf(bn); bd = DXY; }
        else      { vn = v;                   bd = bn * DXY; }
        sv[j] = vn * INVE;
        sb[j] = bd;
        if (rb == 0) vOut[base + j] = vn;
    }
    __syncthreads();

    const int wid = tid >> 5, lane = tid & 31;
    const int r = rb * 8 + wid;
    float u = uIn[base + r];
    if (pabs) u += EPSF * logf(g_a[base + r]);
    const float us = u * INVE;

    const size_t off = (size_t)(base + r) * N;
    const uint2* __restrict__ hp = (const uint2*)(chi_ptr() + off);
    const unsigned* __restrict__ lp = (const unsigned*)(clo_ptr() + off);

    float ac0 = 0.f, ac1 = 0.f, ac2 = 0.f, ac3 = 0.f;
#pragma unroll 4
    for (int s = 0; s < 16; s++) {
        int idx = s * 32 + lane;
        uint2 h = hp[idx];
        unsigned l = lp[idx];
        float4 v4 = *(const float4*)&sv[idx * 4];
        float4 b4 = *(const float4*)&sb[idx * 4];
        unsigned q0 = ((h.x & 0xFFFFu) << 8) | (l & 0xFFu);
        unsigned q1 = ((h.x >> 16) << 8)     | ((l >> 8) & 0xFFu);
        unsigned q2 = ((h.y & 0xFFFFu) << 8) | ((l >> 16) & 0xFFu);
        unsigned q3 = ((h.y >> 16) << 8)     | (l >> 24);
        float k0 = fminf(__expf(fmaf((float)q0, -CS, us + v4.x)), HUGEF);
        float k1 = fminf(__expf(fmaf((float)q1, -CS, us + v4.y)), HUGEF);
        float k2 = fminf(__expf(fmaf((float)q2, -CS, us + v4.z)), HUGEF);
        float k3 = fminf(__expf(fmaf((float)q3, -CS, us + v4.w)), HUGEF);
        ac0 = fmaf(k0, b4.x, ac0);
        ac1 = fmaf(k1, b4.y, ac1);
        ac2 = fmaf(k2, b4.z, ac2);
        ac3 = fmaf(k3, b4.w, ac3);
    }
    float acc = warp_sum((ac0 + ac1) + (ac2 + ac3));
    if (lane == 0) {
        float x = 1.0f / (expf(u) * acc);
        float a = fminf(powf(x, PC), HUGEF);
        g_a[base + r] = a;
        uOut[base + r] = u;
        swm[wid] = a;
    }
    __syncthreads();
    if (tid == 0) {
        float m = swm[0];
#pragma unroll
        for (int k = 1; k < 8; k++) m = fmaxf(m, swm[k]);
        atomicMax(&g_maxa[it], __float_as_uint(m));
    }
}

// ---------------- col pass: partial s2 sums ----------------
__global__ void __launch_bounds__(256) col_kernel(int it) {
    __shared__ float su[128];
    __shared__ float sa[128];
    const int bx = blockIdx.x;            // 256 blocks: b(8) x jt(2) x ic(16)
    const int b  = bx >> 5;
    const int jt = (bx >> 4) & 1;
    const int ic = bx & 15;
    const int tid = threadIdx.x;
    const float* __restrict__ uC = g_u[(it + 1) & 1];
    const float* __restrict__ vC = g_v[(it + 1) & 1];
    const int base = b * N;
    const int i0 = ic * 128;
    if (tid < 128) {
        su[tid] = uC[base + i0 + tid] * INVE;
        sa[tid] = g_a[base + i0 + tid] * DXY;
    }
    const int j0 = jt * 1024 + tid * 4;
    float4 vv = *(const float4*)&vC[base + j0];
    const float vs0 = vv.x * INVE, vs1 = vv.y * INVE, vs2 = vv.z * INVE, vs3 = vv.w * INVE;
    __syncthreads();

    const unsigned short* __restrict__ chi = chi_ptr();
    const unsigned char*  __restrict__ clo = clo_ptr();
    float a0 = 0.f, a1 = 0.f, a2 = 0.f, a3 = 0.f;
    const size_t rb0 = (size_t)(base + i0) * N + j0;
#pragma unroll 4
    for (int i = 0; i < 128; i++) {
        const size_t o = rb0 + (size_t)i * N;
        uint2 h = *(const uint2*)(chi + o);
        unsigned l = *(const unsigned*)(clo + o);
        float ti = su[i];
        float ax = sa[i];
        unsigned q0 = ((h.x & 0xFFFFu) << 8) | (l & 0xFFu);
        unsigned q1 = ((h.x >> 16) << 8)     | ((l >> 8) & 0xFFu);
        unsigned q2 = ((h.y & 0xFFFFu) << 8) | ((l >> 16) & 0xFFu);
        unsigned q3 = ((h.y >> 16) << 8)     | (l >> 24);
        float k0 = fminf(__expf(fmaf((float)q0, -CS, ti + vs0)), HUGEF);
        float k1 = fminf(__expf(fmaf((float)q1, -CS, ti + vs1)), HUGEF);
        float k2 = fminf(__expf(fmaf((float)q2, -CS, ti + vs2)), HUGEF);
        float k3 = fminf(__expf(fmaf((float)q3, -CS, ti + vs3)), HUGEF);
        a0 = fmaf(k0, ax, a0);
        a1 = fmaf(k1, ax, a1);
        a2 = fmaf(k2, ax, a2);
        a3 = fmaf(k3, ax, a3);
    }
    *(float4*)&g_part[ic][base + j0] = make_float4(a0, a1, a2, a3);
}

// ---------------- reduce partials -> b_new, max flag ----------------
__global__ void __launch_bounds__(256) bnew_kernel(int it) {
    const int g = blockIdx.x * 256 + threadIdx.x;   // grid 64
    const float* __restrict__ vC = g_v[(it + 1) & 1];
    float s2 = 0.f;
#pragma unroll
    for (int p = 0; p < NPART; p++) s2 += g_part[p][g];
    float x = 1.0f / (expf(vC[g]) * s2);
    float bn = fminf(powf(x, PC), HUGEF);
    g_bnew[g] = bn;
    __shared__ float sm[256];
    sm[threadIdx.x] = bn;
    __syncthreads();
#pragma unroll
    for (int o = 128; o > 0; o >>= 1) {
        if (threadIdx.x < o) sm[threadIdx.x] = fmaxf(sm[threadIdx.x], sm[threadIdx.x + o]);
        __syncthreads();
    }
    if (threadIdx.x == 0) atomicMax(&g_maxb[it], __float_as_uint(sm[0]));
}

// ---------------- final: K output + row marginals (full precision C) ----------------
__global__ void __launch_bounds__(256) final_row_kernel(const float* __restrict__ C,
                                                        float* __restrict__ KoutArg,
                                                        int useScratch) {
    __shared__ float sv[N];
    float* __restrict__ Kout = useScratch ? (float*)g_buf : KoutArg;
    const int b   = blockIdx.x >> 8;
    const int rb  = blockIdx.x & 255;
    const int tid = threadIdx.x;
    const int base = b * N;
    for (int j = tid; j < N; j += 256) {
        float vn = g_v[0][base + j] + EPSF * logf(g_bnew[base + j]);
        sv[j] = vn * INVE;
    }
    __syncthreads();
    const int wid = tid >> 5, lane = tid & 31;
    const int r = rb * 8 + wid;
    float u = g_u[0][base + r] + EPSF * logf(g_a[base + r]);
    const float us = u * INVE;
    const size_t off = (size_t)(base + r) * N;
    const float4* __restrict__ cp = (const float4*)(C + off);
    float4* __restrict__ kp = (float4*)(Kout + off);
    float accS = 0.f, accC = 0.f;
#pragma unroll 4
    for (int s = 0; s < 16; s++) {
        int idx = s * 32 + lane;
        float4 c = cp[idx];
        float4 v4 = *(const float4*)&sv[idx * 4];
        float4 k;
        k.x = fminf(__expf(fmaf(c.x, -INVE, us + v4.x)), HUGEF);
        k.y = fminf(__expf(fmaf(c.y, -INVE, us + v4.y)), HUGEF);
        k.z = fminf(__expf(fmaf(c.z, -INVE, us + v4.z)), HUGEF);
        k.w = fminf(__expf(fmaf(c.w, -INVE, us + v4.w)), HUGEF);
        kp[idx] = k;
        accS += (k.x + k.y) + (k.z + k.w);
        accC = fmaf(k.x, c.x, accC);
        accC = fmaf(k.y, c.y, accC);
        accC = fmaf(k.z, c.z, accC);
        accC = fmaf(k.w, c.w, accC);
    }
    accS = warp_sum(accS);
    accC = warp_sum(accC);
    if (lane == 0) {
        g_rowsum[base + r] = accS * DXY;
        g_rowkc[base + r]  = accC;
    }
}

// ---------------- final: column marginal partials (read K back) ----------------
__global__ void __launch_bounds__(256) final_col_kernel(const float* __restrict__ KoutArg,
                                                        int useScratch) {
    const float* __restrict__ Kout = useScratch ? (const float*)g_buf : KoutArg;
    const int bx = blockIdx.x;
    const int b  = bx >> 5;
    const int jt = (bx >> 4) & 1;
    const int ic = bx & 15;
    const int tid = threadIdx.x;
    const int base = b * N;
    const int i0 = ic * 128;
    const int j0 = jt * 1024 + tid * 4;
    float a0 = 0.f, a1 = 0.f, a2 = 0.f, a3 = 0.f;
    const size_t rb0 = (size_t)(base + i0) * N + j0;
#pragma unroll 4
    for (int i = 0; i < 128; i++) {
        float4 k = *(const float4*)(Kout + rb0 + (size_t)i * N);
        a0 += k.x; a1 += k.y; a2 += k.z; a3 += k.w;
    }
    *(float4*)&g_part[ic][base + j0] = make_float4(a0, a1, a2, a3);
}

// ---------------- final scalars ----------------
__global__ void __launch_bounds__(256) finalize_kernel(float* __restrict__ out) {
    const int b = blockIdx.x;
    const int tid = threadIdx.x;
    const int base = b * N;
    float c1 = 0.f, c2 = 0.f, tr = 0.f;
    for (int i = tid; i < N; i += 256) {
        float x = g_rowsum[base + i];
        float dv = x / (1.0f + SMALLF);
        c1 += dv * logf(dv + SMALLF) - dv + 1.0f;
        tr += g_rowkc[base + i];
    }
    for (int j = tid; j < N; j += 256) {
        float s = 0.f;
#pragma unroll
        for (int p = 0; p < NPART; p++) s += g_part[p][base + j];
        float x = s * DXY;
        float dv = x / (1.0f + SMALLF);
        c2 += dv * logf(dv + SMALLF) - dv + 1.0f;
    }
    __shared__ float s1[256], s2[256], s3[256];
    s1[tid] = c1; s2[tid] = c2; s3[tid] = tr;
    __syncthreads();
    for (int o = 128; o > 0; o >>= 1) {
        if (tid < o) {
            s1[tid] += s1[tid + o];
            s2[tid] += s2[tid + o];
            s3[tid] += s3[tid + o];
        }
        __syncthreads();
    }
    if (tid == 0) {
        float cons  = 4.0f * (s1[0] * DXY + s2[0] * DXY);
        float trans = 4.0f * s3[0] * DXY * DXY;
        out[b]             = cons + trans;
        out[BATCH + b]     = trans;
        out[2 * BATCH + b] = cons;
    }
}

// ---------------- launch ----------------
extern "C" void kernel_launch(void* const* d_in, const int* in_sizes, int n_in,
                              void* d_out, int out_size) {
    const float* C = (const float*)d_in[0];
    float* out = (float*)d_out;
    const int useScratch = (out_size < (int)(TOTE + 3 * BATCH)) ? 1 : 0;
    float* Kout = out + 3 * BATCH;

    init_kernel<<<64, 256>>>();
    compress_kernel<<<TOTE / 4 / 256, 256>>>(C);
    for (int it = 0; it < NITER; it++) {
        row_kernel<<<2048, 256>>>(it);
        col_kernel<<<256, 256>>>(it);
        bnew_kernel<<<64, 256>>>(it);
    }
    final_row_kernel<<<2048, 256>>>(C, Kout, useScratch);
    final_col_kernel<<<256, 256>>>(Kout, useScratch);
    finalize_kernel<<<BATCH, 256>>>(out);
}

// round 5
// speedup vs baseline: 2.4313x; 2.4313x over previous
#include <cuda_runtime.h>
#include <cuda_fp16.h>
#include <math.h>

#define BATCH 8
#define N 2048
#define BN (BATCH * N)
#define TOTE (BATCH * N * N)          // 33554432 elements
#define NPART 64
#define NITER 50

#define EPSF   0.01f
#define BIGF   1e20f
#define HUGEF  1e30f
#define SMALLF 1e-7f
#define DXY    (1.0f / 2048.0f)

static constexpr float INVE = 1.0f / 0.01f;          // 1/eps
static constexpr float PC   = 1.0f / (1.0f + 0.01f); // p_coef

// ---------------- device state (single big buffer, phase-aliased) ----------------
// Phase 1 (loop):  first 64 MB = K~ in fp16 (exp((u+v-C)/eps) under current u,v)
// Phase 2 (final): whole 128 MB = fallback fp32 K target (K~ dead by then)
static __device__ float4 g_buf[TOTE / 4];        // 128 MB
static __device__ float g_u[BN];
static __device__ float g_v[BN];
static __device__ float g_a[BN];
static __device__ float g_b[BN];
static __device__ float g_part[NPART][BN];       // 4 MB
static __device__ float g_rowsum[BN];
static __device__ float g_rowkc[BN];
static __device__ unsigned g_maxa[64];
static __device__ unsigned g_maxb[64];

__device__ __forceinline__ __half* K_ptr() { return (__half*)g_buf; }

__device__ __forceinline__ float warp_sum(float x) {
#pragma unroll
    for (int o = 16; o; o >>= 1) x += __shfl_xor_sync(0xFFFFFFFFu, x, o);
    return x;
}

// ---------------- init ----------------
__global__ void init_kernel() {
    int g = blockIdx.x * 256 + threadIdx.x;
    if (g < BN) {
        g_u[g] = 0.0f;
        g_v[g] = 0.0f;
        g_b[g] = 1.0f;
    }
    if (g < 64) { g_maxa[g] = 0u; g_maxb[g] = 0u; }
}

// ---------------- build K~ = fp16(exp(-C/eps)) ----------------
__global__ void __launch_bounds__(256) build_kernel(const float* __restrict__ C) {
    size_t idx = (size_t)blockIdx.x * 256 + threadIdx.x;   // covers TOTE/8
    float4 c0 = ((const float4*)C)[2 * idx];
    float4 c1 = ((const float4*)C)[2 * idx + 1];
    __half2 h0 = __floats2half2_rn(__expf(c0.x * -INVE), __expf(c0.y * -INVE));
    __half2 h1 = __floats2half2_rn(__expf(c0.z * -INVE), __expf(c0.w * -INVE));
    __half2 h2 = __floats2half2_rn(__expf(c1.x * -INVE), __expf(c1.y * -INVE));
    __half2 h3 = __floats2half2_rn(__expf(c1.z * -INVE), __expf(c1.w * -INVE));
    uint4 o;
    *reinterpret_cast<__half2*>(&o.x) = h0;
    *reinterpret_cast<__half2*>(&o.y) = h1;
    *reinterpret_cast<__half2*>(&o.z) = h2;
    *reinterpret_cast<__half2*>(&o.w) = h3;
    ((uint4*)K_ptr())[idx] = o;
}

// ---------------- row pass: (optional absorb-rebuild) + s -> a ----------------
__global__ void __launch_bounds__(256) row_kernel(int it) {
    __shared__ __align__(16) float sb[N];   // b_j * dy
    __shared__ float swm[8];
    const int b   = blockIdx.x >> 8;
    const int rb  = blockIdx.x & 255;
    const int tid = threadIdx.x;
    const int prev = (it == 0) ? 63 : (it - 1);
    const bool pabs = (__uint_as_float(g_maxa[prev]) > BIGF) ||
                      (__uint_as_float(g_maxb[prev]) > BIGF);
    const int base = b * N;

    for (int j = tid; j < N; j += 256) {
        float bn = g_b[base + j];
        sb[j] = bn * DXY;
        if (pabs && rb == 0) g_v[base + j] += EPSF * logf(bn);
    }
    __syncthreads();

    const int wid = tid >> 5, lane = tid & 31;
    const int r = rb * 8 + wid;
    float u = g_u[base + r];
    float acc = 0.0f;
    const size_t off = (size_t)(base + r) * N;

    if (!pabs) {
        const uint4* __restrict__ kp = (const uint4*)(K_ptr() + off);
        float a0 = 0.f, a1 = 0.f, a2 = 0.f, a3 = 0.f;
#pragma unroll
        for (int s = 0; s < 8; s++) {
            int idx = s * 32 + lane;
            uint4 p = kp[idx];
            float4 b0 = *(const float4*)&sb[idx * 8];
            float4 b1 = *(const float4*)&sb[idx * 8 + 4];
            float2 f0 = __half22float2(*reinterpret_cast<__half2*>(&p.x));
            float2 f1 = __half22float2(*reinterpret_cast<__half2*>(&p.y));
            float2 f2 = __half22float2(*reinterpret_cast<__half2*>(&p.z));
            float2 f3 = __half22float2(*reinterpret_cast<__half2*>(&p.w));
            a0 = fmaf(f0.x, b0.x, a0); a1 = fmaf(f0.y, b0.y, a1);
            a2 = fmaf(f1.x, b0.z, a2); a3 = fmaf(f1.y, b0.w, a3);
            a0 = fmaf(f2.x, b1.x, a0); a1 = fmaf(f2.y, b1.y, a1);
            a2 = fmaf(f3.x, b1.z, a2); a3 = fmaf(f3.y, b1.w, a3);
        }
        acc = (a0 + a1) + (a2 + a3);
    } else {
        // absorb: K~ <- clip(K~ * a_i * b_j); s = sum K~_new * dy; u <- u + eps*log a
        float aold = g_a[base + r];
        u += EPSF * logf(aold);
        uint4* kp = (uint4*)(K_ptr() + off);
#pragma unroll
        for (int s = 0; s < 8; s++) {
            int idx = s * 32 + lane;
            uint4 p = kp[idx];
            float4 b0 = *(const float4*)&sb[idx * 8];
            float4 b1 = *(const float4*)&sb[idx * 8 + 4];
            float2 f0 = __half22float2(*reinterpret_cast<__half2*>(&p.x));
            float2 f1 = __half22float2(*reinterpret_cast<__half2*>(&p.y));
            float2 f2 = __half22float2(*reinterpret_cast<__half2*>(&p.z));
            float2 f3 = __half22float2(*reinterpret_cast<__half2*>(&p.w));
            // raw b_j = sb[j]*N (exact: N = 2^11)
            float k0 = fminf(f0.x * aold * (b0.x * (float)N), HUGEF);
            float k1 = fminf(f0.y * aold * (b0.y * (float)N), HUGEF);
            float k2 = fminf(f1.x * aold * (b0.z * (float)N), HUGEF);
            float k3 = fminf(f1.y * aold * (b0.w * (float)N), HUGEF);
            float k4 = fminf(f2.x * aold * (b1.x * (float)N), HUGEF);
            float k5 = fminf(f2.y * aold * (b1.y * (float)N), HUGEF);
            float k6 = fminf(f3.x * aold * (b1.z * (float)N), HUGEF);
            float k7 = fminf(f3.y * aold * (b1.w * (float)N), HUGEF);
            acc += ((k0 + k1) + (k2 + k3)) + ((k4 + k5) + (k6 + k7));
            uint4 o;
            *reinterpret_cast<__half2*>(&o.x) = __floats2half2_rn(k0, k1);
            *reinterpret_cast<__half2*>(&o.y) = __floats2half2_rn(k2, k3);
            *reinterpret_cast<__half2*>(&o.z) = __floats2half2_rn(k4, k5);
            *reinterpret_cast<__half2*>(&o.w) = __floats2half2_rn(k6, k7);
            kp[idx] = o;
        }
        acc *= DXY;
    }

    acc = warp_sum(acc);
    if (lane == 0) {
        if (pabs) g_u[base + r] = u;
        float a = fminf(powf(1.0f / (expf(u) * acc), PC), HUGEF);
        g_a[base + r] = a;
        swm[wid] = a;
    }
    __syncthreads();
    if (tid == 0) {
        float m = swm[0];
#pragma unroll
        for (int k = 1; k < 8; k++) m = fmaxf(m, swm[k]);
        atomicMax(&g_maxa[it], __float_as_uint(m));
    }
}

// ---------------- col pass: partial s2 sums ----------------
__global__ void __launch_bounds__(256) col_kernel(int it) {
    __shared__ float sa[32];
    const int bx = blockIdx.x;            // 1024 blocks: b(8) x jt(2) x ic(64)
    const int b  = bx >> 7;
    const int jt = (bx >> 6) & 1;
    const int ic = bx & 63;
    const int tid = threadIdx.x;
    const int base = b * N;
    const int i0 = ic * 32;
    if (tid < 32) sa[tid] = g_a[base + i0 + tid] * DXY;
    __syncthreads();

    const int j0 = jt * 1024 + tid * 4;
    const __half* __restrict__ K = K_ptr();
    float a0 = 0.f, a1 = 0.f, a2 = 0.f, a3 = 0.f;
    const size_t rb0 = (size_t)(base + i0) * N + j0;
#pragma unroll 8
    for (int i = 0; i < 32; i++) {
        uint2 h = *(const uint2*)(K + rb0 + (size_t)i * N);
        float2 f01 = __half22float2(*reinterpret_cast<__half2*>(&h.x));
        float2 f23 = __half22float2(*reinterpret_cast<__half2*>(&h.y));
        float ax = sa[i];
        a0 = fmaf(f01.x, ax, a0);
        a1 = fmaf(f01.y, ax, a1);
        a2 = fmaf(f23.x, ax, a2);
        a3 = fmaf(f23.y, ax, a3);
    }
    *(float4*)&g_part[ic][base + j0] = make_float4(a0, a1, a2, a3);
}

// ---------------- reduce partials -> b, max flag ----------------
__global__ void __launch_bounds__(256) bnew_kernel(int it) {
    const int g = blockIdx.x * 256 + threadIdx.x;   // grid 64
    float s2 = 0.f;
#pragma unroll
    for (int p = 0; p < NPART; p++) s2 += g_part[p][g];
    float bn = fminf(powf(1.0f / (expf(g_v[g]) * s2), PC), HUGEF);
    g_b[g] = bn;
    __shared__ float sm[256];
    sm[threadIdx.x] = bn;
    __syncthreads();
#pragma unroll
    for (int o = 128; o > 0; o >>= 1) {
        if (threadIdx.x < o) sm[threadIdx.x] = fmaxf(sm[threadIdx.x], sm[threadIdx.x + o]);
        __syncthreads();
    }
    if (threadIdx.x == 0) atomicMax(&g_maxb[it], __float_as_uint(sm[0]));
}

// ---------------- final: K output + row marginals (full precision C) ----------------
__global__ void __launch_bounds__(256) final_row_kernel(const float* __restrict__ C,
                                                        float* __restrict__ KoutArg,
                                                        int useScratch) {
    __shared__ __align__(16) float sv[N];
    float* __restrict__ Kout = useScratch ? (float*)g_buf : KoutArg;
    const int b   = blockIdx.x >> 8;
    const int rb  = blockIdx.x & 255;
    const int tid = threadIdx.x;
    const int base = b * N;
    for (int j = tid; j < N; j += 256) {
        float vn = g_v[base + j] + EPSF * logf(g_b[base + j]);
        sv[j] = vn * INVE;
    }
    __syncthreads();
    const int wid = tid >> 5, lane = tid & 31;
    const int r = rb * 8 + wid;
    float u = g_u[base + r] + EPSF * logf(g_a[base + r]);
    const float us = u * INVE;
    const size_t off = (size_t)(base + r) * N;
    const float4* __restrict__ cp = (const float4*)(C + off);
    float4* __restrict__ kp = (float4*)(Kout + off);
    float accS = 0.f, accC = 0.f;
#pragma unroll 4
    for (int s = 0; s < 16; s++) {
        int idx = s * 32 + lane;
        float4 c = cp[idx];
        float4 v4 = *(const float4*)&sv[idx * 4];
        float4 k;
        k.x = fminf(__expf(fmaf(c.x, -INVE, us + v4.x)), HUGEF);
        k.y = fminf(__expf(fmaf(c.y, -INVE, us + v4.y)), HUGEF);
        k.z = fminf(__expf(fmaf(c.z, -INVE, us + v4.z)), HUGEF);
        k.w = fminf(__expf(fmaf(c.w, -INVE, us + v4.w)), HUGEF);
        kp[idx] = k;
        accS += (k.x + k.y) + (k.z + k.w);
        accC = fmaf(k.x, c.x, accC);
        accC = fmaf(k.y, c.y, accC);
        accC = fmaf(k.z, c.z, accC);
        accC = fmaf(k.w, c.w, accC);
    }
    accS = warp_sum(accS);
    accC = warp_sum(accC);
    if (lane == 0) {
        g_rowsum[base + r] = accS * DXY;
        g_rowkc[base + r]  = accC;
    }
}

// ---------------- final: column marginal partials (read K back) ----------------
__global__ void __launch_bounds__(256) final_col_kernel(const float* __restrict__ KoutArg,
                                                        int useScratch) {
    const float* __restrict__ Kout = useScratch ? (const float*)g_buf : KoutArg;
    const int bx = blockIdx.x;            // 1024 blocks: b(8) x jt(2) x ic(64)
    const int b  = bx >> 7;
    const int jt = (bx >> 6) & 1;
    const int ic = bx & 63;
    const int tid = threadIdx.x;
    const int base = b * N;
    const int i0 = ic * 32;
    const int j0 = jt * 1024 + tid * 4;
    float a0 = 0.f, a1 = 0.f, a2 = 0.f, a3 = 0.f;
    const size_t rb0 = (size_t)(base + i0) * N + j0;
#pragma unroll 8
    for (int i = 0; i < 32; i++) {
        float4 k = *(const float4*)(Kout + rb0 + (size_t)i * N);
        a0 += k.x; a1 += k.y; a2 += k.z; a3 += k.w;
    }
    *(float4*)&g_part[ic][base + j0] = make_float4(a0, a1, a2, a3);
}

// ---------------- final scalars ----------------
__global__ void __launch_bounds__(256) finalize_kernel(float* __restrict__ out) {
    const int b = blockIdx.x;
    const int tid = threadIdx.x;
    const int base = b * N;
    float c1 = 0.f, c2 = 0.f, tr = 0.f;
    for (int i = tid; i < N; i += 256) {
        float x = g_rowsum[base + i];
        float dv = x / (1.0f + SMALLF);
        c1 += dv * logf(dv + SMALLF) - dv + 1.0f;
        tr += g_rowkc[base + i];
    }
    for (int j = tid; j < N; j += 256) {
        float s = 0.f;
#pragma unroll
        for (int p = 0; p < NPART; p++) s += g_part[p][base + j];
        float x = s * DXY;
        float dv = x / (1.0f + SMALLF);
        c2 += dv * logf(dv + SMALLF) - dv + 1.0f;
    }
    __shared__ float s1[256], s2[256], s3[256];
    s1[tid] = c1; s2[tid] = c2; s3[tid] = tr;
    __syncthreads();
    for (int o = 128; o > 0; o >>= 1) {
        if (tid < o) {
            s1[tid] += s1[tid + o];
            s2[tid] += s2[tid + o];
            s3[tid] += s3[tid + o];
        }
        __syncthreads();
    }
    if (tid == 0) {
        float cons  = 4.0f * (s1[0] * DXY + s2[0] * DXY);
        float trans = 4.0f * s3[0] * DXY * DXY;
        out[b]             = cons + trans;
        out[BATCH + b]     = trans;
        out[2 * BATCH + b] = cons;
    }
}

// ---------------- launch ----------------
extern "C" void kernel_launch(void* const* d_in, const int* in_sizes, int n_in,
                              void* d_out, int out_size) {
    const float* C = (const float*)d_in[0];
    float* out = (float*)d_out;
    const int useScratch = (out_size < (int)(TOTE + 3 * BATCH)) ? 1 : 0;
    float* Kout = out + 3 * BATCH;

    init_kernel<<<64, 256>>>();
    build_kernel<<<TOTE / 8 / 256, 256>>>(C);
    for (int it = 0; it < NITER; it++) {
        row_kernel<<<2048, 256>>>(it);
        col_kernel<<<1024, 256>>>(it);
        bnew_kernel<<<64, 256>>>(it);
    }
    final_row_kernel<<<2048, 256>>>(C, Kout, useScratch);
    final_col_kernel<<<1024, 256>>>(Kout, useScratch);
    finalize_kernel<<<BATCH, 256>>>(out);
}